// round 2
// baseline (speedup 1.0000x reference)
#include <cuda_runtime.h>
#include <cuda_bf16.h>
#include <cstdint>

#define M_IDS   65536
#define N_HID   768
#define K_FEAT  220
#define K_PAD   224
#define NDOCS   128
#define NQUER   2000

// Scratch (allocation-free rule: __device__ globals)
__device__ __nv_bfloat16 g_Ahi[M_IDS * K_PAD];
__device__ __nv_bfloat16 g_Alo[M_IDS * K_PAD];
__device__ __nv_bfloat16 g_Whi[N_HID * K_PAD];
__device__ __nv_bfloat16 g_Wlo[N_HID * K_PAD];
__device__ int g_ids_is_i32;

// ---------------------------------------------------------------------------
// Kernel 0: detect whether ids buffer is int64 (odd 32-bit words all zero)
// or int32 pairs (odd words = did, almost surely nonzero somewhere).
// ---------------------------------------------------------------------------
__global__ void detect_ids_kernel(const int* __restrict__ w) {
    int any = 0;
    for (int i = threadIdx.x; i < 2048; i += 32) any |= w[2 * i + 1];
    any = __reduce_or_sync(0xffffffffu, any);
    if (threadIdx.x == 0) g_ids_is_i32 = (any != 0) ? 1 : 0;
}

// ---------------------------------------------------------------------------
// Kernel 1: split W into bf16 hi/lo planes, zero-padded to K_PAD
// ---------------------------------------------------------------------------
__global__ void wprep_kernel(const float* __restrict__ W) {
    int idx = blockIdx.x * blockDim.x + threadIdx.x;
    if (idx >= N_HID * K_PAD) return;
    int row = idx / K_PAD;
    int k   = idx - row * K_PAD;
    float v = (k < K_FEAT) ? W[row * K_FEAT + k] : 0.0f;
    __nv_bfloat16 hi = __float2bfloat16(v);
    g_Whi[idx] = hi;
    g_Wlo[idx] = __float2bfloat16(v - __bfloat162float(hi));
}

// ---------------------------------------------------------------------------
// Kernel 2: gather + log1p(|x|)*sign(x), write feature_batch + bf16 hi/lo
// ---------------------------------------------------------------------------
__global__ void gather_transform_kernel(const int* __restrict__ ids32,
                                        const float* __restrict__ table,
                                        float* __restrict__ fb_out,
                                        int write_fb) {
    int idx = blockIdx.x * blockDim.x + threadIdx.x;
    if (idx >= M_IDS * K_PAD) return;
    int row = idx / K_PAD;
    int k   = idx - row * K_PAD;
    float v = 0.0f;
    if (k < K_FEAT) {
        int q, d;
        if (g_ids_is_i32) {           // int32 pairs: [q, d, q, d, ...]
            q = ids32[2 * row];
            d = ids32[2 * row + 1];
        } else {                      // int64 LE: [q_lo, q_hi(0), d_lo, d_hi(0), ...]
            q = ids32[4 * row];
            d = ids32[4 * row + 2];
        }
        q = min(max(q, 0), NQUER - 1);
        d = min(max(d, 0), NDOCS - 1);
        float x = table[((long long)q * NDOCS + d) * K_FEAT + k];
        v = copysignf(logf(fabsf(x) + 1.0f), x);
        if (write_fb) fb_out[row * K_FEAT + k] = v;
    }
    __nv_bfloat16 hi = __float2bfloat16(v);
    g_Ahi[idx] = hi;
    g_Alo[idx] = __float2bfloat16(v - __bfloat162float(hi));
}

// ---------------------------------------------------------------------------
// Kernel 3: GEMM  C[M,N] = relu(A[M,K] * W[N,K]^T + b)  via bf16 3-term split
// Block tile 128x128, K-step 32, 8 warps, warp tile 32x64, mma.m16n8k16
// ---------------------------------------------------------------------------
#define BM  128
#define BN  128
#define BK  32
#define BKP 40   // +8 bf16 pad -> conflict-free LDS

__device__ __forceinline__ void mma_bf16(float* c, const uint32_t* a, const uint32_t* b) {
    asm volatile(
        "mma.sync.aligned.m16n8k16.row.col.f32.bf16.bf16.f32 "
        "{%0,%1,%2,%3}, {%4,%5,%6,%7}, {%8,%9}, {%0,%1,%2,%3};\n"
        : "+f"(c[0]), "+f"(c[1]), "+f"(c[2]), "+f"(c[3])
        : "r"(a[0]), "r"(a[1]), "r"(a[2]), "r"(a[3]), "r"(b[0]), "r"(b[1]));
}

__global__ __launch_bounds__(256)
void gemm_kernel(const float* __restrict__ bias, float* __restrict__ C) {
    __shared__ __nv_bfloat16 sAhi[BM][BKP];
    __shared__ __nv_bfloat16 sAlo[BM][BKP];
    __shared__ __nv_bfloat16 sBhi[BN][BKP];
    __shared__ __nv_bfloat16 sBlo[BN][BKP];

    const int tid = threadIdx.x;
    const int m0 = blockIdx.y * BM;
    const int n0 = blockIdx.x * BN;

    const int warp = tid >> 5;
    const int lane = tid & 31;
    const int wm = warp >> 1;        // 0..3 -> M offset wm*32
    const int wn = warp & 1;         // 0..1 -> N offset wn*64
    const int g  = lane >> 2;        // 0..7
    const int t  = lane & 3;         // 0..3

    float acc[2][8][4];
#pragma unroll
    for (int i = 0; i < 2; i++)
#pragma unroll
        for (int j = 0; j < 8; j++)
#pragma unroll
            for (int c = 0; c < 4; c++) acc[i][j][c] = 0.0f;

    for (int k0 = 0; k0 < K_PAD; k0 += BK) {
        // ---- load tiles: 512 16B-chunks per array, 2 per thread ----
#pragma unroll
        for (int i = 0; i < 2; i++) {
            int c   = tid + i * 256;
            int row = c >> 2;            // 0..127
            int col = (c & 3) << 3;      // 0,8,16,24
            *(uint4*)&sAhi[row][col] = *(const uint4*)&g_Ahi[(m0 + row) * K_PAD + k0 + col];
            *(uint4*)&sAlo[row][col] = *(const uint4*)&g_Alo[(m0 + row) * K_PAD + k0 + col];
            *(uint4*)&sBhi[row][col] = *(const uint4*)&g_Whi[(n0 + row) * K_PAD + k0 + col];
            *(uint4*)&sBlo[row][col] = *(const uint4*)&g_Wlo[(n0 + row) * K_PAD + k0 + col];
        }
        __syncthreads();

#pragma unroll
        for (int ks = 0; ks < 2; ks++) {
            uint32_t ah[2][4], al[2][4], bh[8][2], bl[8][2];
            const int kk = ks * 16 + t * 2;
#pragma unroll
            for (int mt = 0; mt < 2; mt++) {
                int r = wm * 32 + mt * 16 + g;
                ah[mt][0] = *(const uint32_t*)&sAhi[r][kk];
                ah[mt][1] = *(const uint32_t*)&sAhi[r + 8][kk];
                ah[mt][2] = *(const uint32_t*)&sAhi[r][kk + 8];
                ah[mt][3] = *(const uint32_t*)&sAhi[r + 8][kk + 8];
                al[mt][0] = *(const uint32_t*)&sAlo[r][kk];
                al[mt][1] = *(const uint32_t*)&sAlo[r + 8][kk];
                al[mt][2] = *(const uint32_t*)&sAlo[r][kk + 8];
                al[mt][3] = *(const uint32_t*)&sAlo[r + 8][kk + 8];
            }
#pragma unroll
            for (int nt = 0; nt < 8; nt++) {
                int cc = wn * 64 + nt * 8 + g;
                bh[nt][0] = *(const uint32_t*)&sBhi[cc][kk];
                bh[nt][1] = *(const uint32_t*)&sBhi[cc][kk + 8];
                bl[nt][0] = *(const uint32_t*)&sBlo[cc][kk];
                bl[nt][1] = *(const uint32_t*)&sBlo[cc][kk + 8];
            }
#pragma unroll
            for (int mt = 0; mt < 2; mt++)
#pragma unroll
                for (int nt = 0; nt < 8; nt++) {
                    mma_bf16(acc[mt][nt], ah[mt], bh[nt]);  // hi*hi
                    mma_bf16(acc[mt][nt], ah[mt], bl[nt]);  // hi*lo
                    mma_bf16(acc[mt][nt], al[mt], bh[nt]);  // lo*hi
                }
        }
        __syncthreads();
    }

    // ---- epilogue: bias + relu, float2 stores ----
#pragma unroll
    for (int mt = 0; mt < 2; mt++) {
        int r0 = m0 + wm * 32 + mt * 16 + g;
#pragma unroll
        for (int nt = 0; nt < 8; nt++) {
            int c0 = n0 + wn * 64 + nt * 8 + t * 2;
            float b0 = bias[c0];
            float b1 = bias[c0 + 1];
            float2 v0, v1;
            v0.x = fmaxf(acc[mt][nt][0] + b0, 0.0f);
            v0.y = fmaxf(acc[mt][nt][1] + b1, 0.0f);
            v1.x = fmaxf(acc[mt][nt][2] + b0, 0.0f);
            v1.y = fmaxf(acc[mt][nt][3] + b1, 0.0f);
            *(float2*)&C[(long long)r0 * N_HID + c0]       = v0;
            *(float2*)&C[(long long)(r0 + 8) * N_HID + c0] = v1;
        }
    }
}

// ---------------------------------------------------------------------------
extern "C" void kernel_launch(void* const* d_in, const int* in_sizes, int n_in,
                              void* d_out, int out_size) {
    // Identify inputs robustly by element count.
    const int*   ids32 = nullptr;   // raw words; layout detected on device
    const float* table = nullptr;
    const float* W     = nullptr;
    const float* b     = nullptr;
    for (int i = 0; i < n_in; i++) {
        if (in_sizes[i] == M_IDS * 2)                  ids32 = (const int*)d_in[i];
        else if (in_sizes[i] == NQUER * NDOCS * K_FEAT) table = (const float*)d_in[i];
        else if (in_sizes[i] == N_HID * K_FEAT)        W     = (const float*)d_in[i];
        else if (in_sizes[i] == N_HID)                 b     = (const float*)d_in[i];
    }

    float* out    = (float*)d_out;
    float* C      = out;                               // [65536, 768]
    float* fb_out = out + (long long)M_IDS * N_HID;    // [65536, 220]
    // Only write the second output if d_out actually has room for it.
    int write_fb = (out_size >= M_IDS * (N_HID + K_FEAT)) ? 1 : 0;

    detect_ids_kernel<<<1, 32>>>(ids32);
    wprep_kernel<<<(N_HID * K_PAD + 255) / 256, 256>>>(W);
    gather_transform_kernel<<<(M_IDS * K_PAD + 255) / 256, 256>>>(ids32, table, fb_out, write_fb);

    dim3 grid(N_HID / BN, M_IDS / BM);   // (6, 512): N-tiles fastest -> A-tile L2 reuse
    gemm_kernel<<<grid, 256>>>(b, C);
}

// round 6
// speedup vs baseline: 1.7345x; 1.7345x over previous
#include <cuda_runtime.h>
#include <cuda_bf16.h>
#include <cstdint>

#define M_IDS   65536
#define N_HID   768
#define K_FEAT  220
#define KP      256
#define NDOCS   128
#define NQUER   2000

// ---------------- scratch (__device__ globals; no allocation allowed) -------
__device__ __nv_bfloat16 g_Ahi[(size_t)M_IDS * KP];
__device__ __nv_bfloat16 g_Alo[(size_t)M_IDS * KP];
__device__ __nv_bfloat16 g_Whi[N_HID * KP];
__device__ __nv_bfloat16 g_Wlo[N_HID * KP];
__device__ int g_ids_is_i32;

// tcgen05 is an arch-accelerated feature: only available when compiling for
// sm_103a (feature macro), NOT in the portable compute_103 PTX pass.
#if defined(__CUDA_ARCH__) && defined(__CUDA_ARCH_FEAT_SM103_ALL)
#define HAS_TCGEN05 1
#else
#define HAS_TCGEN05 0
#endif

// ---------------- small PTX helpers ----------------------------------------
__device__ __forceinline__ uint32_t smem_u32(const void* p) {
    uint32_t a;
    asm("{ .reg .u64 t; cvta.to.shared.u64 t, %1; cvt.u32.u64 %0, t; }" : "=r"(a) : "l"(p));
    return a;
}

#if HAS_TCGEN05

#define MBAR_INIT(addr, cnt) \
    asm volatile("mbarrier.init.shared.b64 [%0], %1;" :: "r"(addr), "r"(cnt) : "memory")

#define MBAR_WAIT(addr, par) do {                                              \
    uint32_t _m = (addr); uint32_t _p = (par); uint32_t _done;                 \
    asm volatile("{\n\t.reg .pred p;\n\t"                                      \
        "mbarrier.try_wait.parity.acquire.cta.shared::cta.b64 p, [%1], %2;\n\t"\
        "selp.b32 %0, 1, 0, p;\n\t}"                                           \
        : "=r"(_done) : "r"(_m), "r"(_p) : "memory");                          \
    if (!_done) {                                                              \
        asm volatile("{\n\t.reg .pred P1;\n\t"                                 \
            "W_%=:\n\t"                                                        \
            "mbarrier.try_wait.parity.acquire.cta.shared::cta.b64 P1, [%0], %1, 0x989680;\n\t" \
            "@P1 bra.uni D_%=;\n\t"                                            \
            "bra.uni W_%=;\n\t"                                                \
            "D_%=:\n\t}" :: "r"(_m), "r"(_p) : "memory");                      \
    }                                                                          \
} while (0)

// 64-bit SMEM descriptor: SW128, version=1 (Blackwell), LBO=1, SBO=64
__device__ __forceinline__ uint64_t make_desc_sw128(uint32_t addr) {
    const uint64_t base = (uint64_t(2) << 61) | (uint64_t(1) << 46)
                        | (uint64_t(64) << 32) | (uint64_t(1) << 16);
    return base | ((uint64_t)(addr >> 4) & 0x3FFF);
}

// cta_group::1 kind::f16 SS MMA (bf16 in, fp32 accum in TMEM)
__device__ __forceinline__ void mma_f16_ss(uint32_t d_tmem, uint64_t a_desc,
                                           uint64_t b_desc, uint32_t idesc,
                                           uint32_t enable) {
    asm volatile(
        "{\n\t.reg .pred p;\n\t"
        "setp.ne.u32 p, %5, 0;\n\t"
        "tcgen05.mma.cta_group::1.kind::f16 [%0], %1, %2, %3, {%4, %4, %4, %4}, p;\n\t"
        "}"
        :: "r"(d_tmem), "l"(a_desc), "l"(b_desc), "r"(idesc), "r"(0u), "r"(enable)
        : "memory");
}

#define TC_COMMIT(mbar) \
    asm volatile("tcgen05.commit.cta_group::1.mbarrier::arrive::one.shared::cluster.b64 [%0];" \
                 :: "r"(mbar) : "memory")
#define TC_ALLOC(smem_res, n) \
    asm volatile("tcgen05.alloc.cta_group::1.sync.aligned.shared::cta.b32 [%0], %1;" \
                 :: "r"(smem_res), "r"(n) : "memory")
#define TC_RELINQ() \
    asm volatile("tcgen05.relinquish_alloc_permit.cta_group::1.sync.aligned;")
#define TC_DEALLOC(tmem, n) \
    asm volatile("tcgen05.dealloc.cta_group::1.sync.aligned.b32 %0, %1;" :: "r"(tmem), "r"(n))
#define TC_FENCE_AFTER()  asm volatile("tcgen05.fence::after_thread_sync;" ::: "memory")
#define TC_FENCE_BEFORE() asm volatile("tcgen05.fence::before_thread_sync;" ::: "memory")
#define TC_WAIT_LD()      asm volatile("tcgen05.wait::ld.sync.aligned;" ::: "memory")

#define TC_LD_X32(r, addr)                                                     \
    asm volatile("tcgen05.ld.sync.aligned.32x32b.x32.b32 "                     \
        "{%0,%1,%2,%3,%4,%5,%6,%7,%8,%9,%10,%11,%12,%13,%14,%15,"              \
        "%16,%17,%18,%19,%20,%21,%22,%23,%24,%25,%26,%27,%28,%29,%30,%31}, [%32];" \
        : "=r"((r)[0]),"=r"((r)[1]),"=r"((r)[2]),"=r"((r)[3]),                 \
          "=r"((r)[4]),"=r"((r)[5]),"=r"((r)[6]),"=r"((r)[7]),                 \
          "=r"((r)[8]),"=r"((r)[9]),"=r"((r)[10]),"=r"((r)[11]),               \
          "=r"((r)[12]),"=r"((r)[13]),"=r"((r)[14]),"=r"((r)[15]),             \
          "=r"((r)[16]),"=r"((r)[17]),"=r"((r)[18]),"=r"((r)[19]),             \
          "=r"((r)[20]),"=r"((r)[21]),"=r"((r)[22]),"=r"((r)[23]),             \
          "=r"((r)[24]),"=r"((r)[25]),"=r"((r)[26]),"=r"((r)[27]),             \
          "=r"((r)[28]),"=r"((r)[29]),"=r"((r)[30]),"=r"((r)[31])              \
        : "r"(addr))

#endif  // HAS_TCGEN05

// ---------------------------------------------------------------------------
// Kernel 0: ids layout detection (int64 LE vs int32 pairs)
// ---------------------------------------------------------------------------
__global__ void detect_ids_kernel(const int* __restrict__ w) {
    int any = 0;
    for (int i = threadIdx.x; i < 2048; i += 32) any |= w[2 * i + 1];
    any = __reduce_or_sync(0xffffffffu, any);
    if (threadIdx.x == 0) g_ids_is_i32 = (any != 0) ? 1 : 0;
}

// ---------------------------------------------------------------------------
// Kernel 1: split W -> bf16 hi/lo planes, zero-padded to KP
// ---------------------------------------------------------------------------
__global__ void wprep_kernel(const float* __restrict__ W) {
    int idx = blockIdx.x * blockDim.x + threadIdx.x;
    if (idx >= N_HID * KP) return;
    int row = idx / KP;
    int k   = idx - row * KP;
    float v = (k < K_FEAT) ? W[row * K_FEAT + k] : 0.0f;
    __nv_bfloat16 hi = __float2bfloat16(v);
    g_Whi[idx] = hi;
    g_Wlo[idx] = __float2bfloat16(v - __bfloat162float(hi));
}

// ---------------------------------------------------------------------------
// Kernel 2: gather + log1p(|x|)*sign(x), vectorized; writes fb + hi/lo planes
// 1 warp per row; thread j handles float4 chunks 2j, 2j+1 (padded K=256)
// ---------------------------------------------------------------------------
__device__ __forceinline__ uint32_t pack2bf(float a, float b) {
    __nv_bfloat162 t = __floats2bfloat162_rn(a, b);
    return *(uint32_t*)&t;
}

__global__ __launch_bounds__(256)
void gather_transform_kernel(const int* __restrict__ ids32,
                             const float* __restrict__ table,
                             float* __restrict__ fb, int write_fb) {
    int r = blockIdx.x * 8 + (threadIdx.x >> 5);
    int j = threadIdx.x & 31;
    int q, d;
    if (g_ids_is_i32) { q = ids32[2 * r]; d = ids32[2 * r + 1]; }
    else              { q = ids32[4 * r]; d = ids32[4 * r + 2]; }
    q = min(max(q, 0), NQUER - 1);
    d = min(max(d, 0), NDOCS - 1);
    const float4* src = (const float4*)(table + ((size_t)q * NDOCS + d) * K_FEAT);
#pragma unroll
    for (int t = 0; t < 2; t++) {
        int c4 = j * 2 + t;           // 0..63
        int k  = c4 * 4;              // 0..252
        float4 x = make_float4(0.f, 0.f, 0.f, 0.f);
        bool valid = (k < K_FEAT);    // K_FEAT % 4 == 0 -> whole float4 valid
        if (valid) x = src[c4];
        float4 v;
        v.x = copysignf(__logf(fabsf(x.x) + 1.0f), x.x);
        v.y = copysignf(__logf(fabsf(x.y) + 1.0f), x.y);
        v.z = copysignf(__logf(fabsf(x.z) + 1.0f), x.z);
        v.w = copysignf(__logf(fabsf(x.w) + 1.0f), x.w);
        if (valid && write_fb) *(float4*)&fb[(size_t)r * K_FEAT + k] = v;

        __nv_bfloat16 h0 = __float2bfloat16(v.x), h1 = __float2bfloat16(v.y);
        __nv_bfloat16 h2 = __float2bfloat16(v.z), h3 = __float2bfloat16(v.w);
        float l0 = v.x - __bfloat162float(h0), l1 = v.y - __bfloat162float(h1);
        float l2 = v.z - __bfloat162float(h2), l3 = v.w - __bfloat162float(h3);
        uint2 hiw, low;
        hiw.x = pack2bf(__bfloat162float(h0), __bfloat162float(h1));
        hiw.y = pack2bf(__bfloat162float(h2), __bfloat162float(h3));
        low.x = pack2bf(l0, l1);
        low.y = pack2bf(l2, l3);
        *(uint2*)&g_Ahi[(size_t)r * KP + k] = hiw;
        *(uint2*)&g_Alo[(size_t)r * KP + k] = low;
    }
}

// ---------------------------------------------------------------------------
// Kernel 3: tcgen05 GEMM  C[M,N] = relu(A @ W^T + b), bf16 3-term split
// CTA tile 128x256, K-chunks of 64, 2-stage smem pipeline, TMEM accumulator
// ---------------------------------------------------------------------------
#define GBM 128
#define GBN 256
#define KC  64
#define NCH (KP / KC)            // 4
#define ST_A 16384               // one A plane chunk: 128 rows x 128B
#define ST_B 32768               // one B plane chunk: 256 rows x 128B
#define STAGE (2*ST_A + 2*ST_B)  // 98304
#define AUX (2 * STAGE)          // 196608
#define OFF_TMEMPTR (AUX + 0)
#define OFF_MBAR    (AUX + 8)    // mbar[0]=+8, mbar[1]=+16
#define OFF_BIAS    (AUX + 128)
#define SMEM_TOTAL  (AUX + 128 + GBN * 4)

static constexpr uint32_t IDESC =
    (1u << 4) | (1u << 7) | (1u << 10) | ((GBN / 8) << 17) | ((GBM / 16) << 24);

__global__ __launch_bounds__(256, 1)
void gemm_tc_kernel(const float* __restrict__ bias, float* __restrict__ C) {
#if HAS_TCGEN05
    extern __shared__ char sm[];
    const uint32_t sb = smem_u32(sm);
    const int tid = threadIdx.x;
    const int warp = tid >> 5, lane = tid & 31;
    const int n0 = blockIdx.x * GBN;
    const int m0 = blockIdx.y * GBM;

    if (warp == 0) {
        TC_ALLOC(sb + OFF_TMEMPTR, 256);
        TC_RELINQ();
    }
    if (tid == 0) {
        MBAR_INIT(sb + OFF_MBAR + 0, 1);
        MBAR_INIT(sb + OFF_MBAR + 8, 1);
    }
    ((float*)(sm + OFF_BIAS))[tid] = bias[n0 + tid];
    __syncthreads();
    uint32_t tmem;
    asm volatile("ld.shared.b32 %0, [%1];" : "=r"(tmem) : "r"(sb + OFF_TMEMPTR));

    for (int c = 0; c < NCH; c++) {
        const int s = c & 1;
        if (c >= 2) {
            MBAR_WAIT(sb + OFF_MBAR + s * 8, ((c >> 1) - 1) & 1);
        }
        const int kb = c * KC;
        // A planes: 2048 uint4
#pragma unroll
        for (int i = tid; i < 2048; i += 256) {
            int pl = i >> 10, row = (i >> 3) & 127, c16 = i & 7;
            const __nv_bfloat16* srcp = pl ? g_Alo : g_Ahi;
            uint4 v = *(const uint4*)&srcp[(size_t)(m0 + row) * KP + kb + c16 * 8];
            uint32_t off = (uint32_t)(row * 128 + c16 * 16);
            *(uint4*)(sm + s * STAGE + pl * ST_A + (off ^ ((off >> 3) & 0x70))) = v;
        }
        // B planes: 4096 uint4
#pragma unroll
        for (int i = tid; i < 4096; i += 256) {
            int pl = i >> 11, row = (i >> 3) & 255, c16 = i & 7;
            const __nv_bfloat16* srcp = pl ? g_Wlo : g_Whi;
            uint4 v = *(const uint4*)&srcp[(size_t)(n0 + row) * KP + kb + c16 * 8];
            uint32_t off = (uint32_t)(row * 128 + c16 * 16);
            *(uint4*)(sm + s * STAGE + 2 * ST_A + pl * ST_B + (off ^ ((off >> 3) & 0x70))) = v;
        }
        __syncthreads();
        if (tid == 0) {
            asm volatile("fence.proxy.async.shared::cta;" ::: "memory");
            uint64_t dA[2] = { make_desc_sw128(sb + s * STAGE),
                               make_desc_sw128(sb + s * STAGE + ST_A) };
            uint64_t dB[2] = { make_desc_sw128(sb + s * STAGE + 2 * ST_A),
                               make_desc_sw128(sb + s * STAGE + 2 * ST_A + ST_B) };
#pragma unroll
            for (int p = 0; p < 3; p++) {
                uint64_t ad = dA[p == 2 ? 1 : 0];
                uint64_t bd = dB[p == 1 ? 1 : 0];
#pragma unroll
                for (int k = 0; k < 4; k++) {
                    uint32_t en = (c == 0 && p == 0 && k == 0) ? 0u : 1u;
                    mma_f16_ss(tmem, ad + 2 * k, bd + 2 * k, IDESC, en);
                }
            }
            TC_COMMIT(sb + OFF_MBAR + s * 8);
        }
    }

    // wait for last commit (chunk NCH-1 -> mbar[1], its 2nd commit -> parity 1)
    MBAR_WAIT(sb + OFF_MBAR + 8, 1);
    TC_FENCE_AFTER();

    // epilogue: 8 warps; warps 0-3 -> cols 0..127, warps 4-7 -> cols 128..255
    const int half = warp >> 2;
    const int mrow = m0 + (warp & 3) * 32 + lane;
    const float* bs = (const float*)(sm + OFF_BIAS);
#pragma unroll
    for (int p = 0; p < 4; p++) {
        const int cb = half * 128 + p * 32;
        uint32_t r[32];
        TC_LD_X32(r, tmem + cb);
        TC_WAIT_LD();
        float o[32];
#pragma unroll
        for (int cc = 0; cc < 32; cc++)
            o[cc] = fmaxf(__uint_as_float(r[cc]) + bs[cb + cc], 0.0f);
        float* dst = &C[(size_t)mrow * N_HID + n0 + cb];
#pragma unroll
        for (int v4 = 0; v4 < 8; v4++) {
            float4 t = make_float4(o[v4 * 4], o[v4 * 4 + 1], o[v4 * 4 + 2], o[v4 * 4 + 3]);
            *(float4*)&dst[v4 * 4] = t;
        }
    }
    TC_FENCE_BEFORE();
    __syncthreads();
    if (warp == 0) TC_DEALLOC(tmem, 256);
#else
    // Portable-PTX fallback (only ever used if the runtime JITs from
    // compute_103 PTX instead of loading the sm_103a cubin). Correct, slow.
    const int tid = threadIdx.x;
    const int n0 = blockIdx.x * GBN, m0 = blockIdx.y * GBM;
    for (int idx = tid; idx < GBM * GBN; idx += blockDim.x) {
        int mi = idx / GBN, ni = idx - mi * GBN;
        float acc = 0.0f;
        for (int k = 0; k < KP; k++) {
            float a = __bfloat162float(g_Ahi[(size_t)(m0 + mi) * KP + k])
                    + __bfloat162float(g_Alo[(size_t)(m0 + mi) * KP + k]);
            float w = __bfloat162float(g_Whi[(size_t)(n0 + ni) * KP + k])
                    + __bfloat162float(g_Wlo[(size_t)(n0 + ni) * KP + k]);
            acc += a * w;
        }
        C[(size_t)(m0 + mi) * N_HID + n0 + ni] = fmaxf(acc + bias[n0 + ni], 0.0f);
    }
#endif
}

// ---------------------------------------------------------------------------
extern "C" void kernel_launch(void* const* d_in, const int* in_sizes, int n_in,
                              void* d_out, int out_size) {
    const int*   ids32 = nullptr;
    const float* table = nullptr;
    const float* W     = nullptr;
    const float* b     = nullptr;
    for (int i = 0; i < n_in; i++) {
        if (in_sizes[i] == M_IDS * 2)                   ids32 = (const int*)d_in[i];
        else if (in_sizes[i] == NQUER * NDOCS * K_FEAT) table = (const float*)d_in[i];
        else if (in_sizes[i] == N_HID * K_FEAT)         W     = (const float*)d_in[i];
        else if (in_sizes[i] == N_HID)                  b     = (const float*)d_in[i];
    }

    float* out    = (float*)d_out;
    float* C      = out;                               // [65536, 768]
    float* fb_out = out + (size_t)M_IDS * N_HID;       // [65536, 220]
    int write_fb  = (out_size >= M_IDS * (N_HID + K_FEAT)) ? 1 : 0;

    cudaFuncSetAttribute(gemm_tc_kernel,
                         cudaFuncAttributeMaxDynamicSharedMemorySize, SMEM_TOTAL);

    detect_ids_kernel<<<1, 32>>>(ids32);
    wprep_kernel<<<(N_HID * KP + 255) / 256, 256>>>(W);
    gather_transform_kernel<<<M_IDS / 8, 256>>>(ids32, table, fb_out, write_fb);

    dim3 grid(N_HID / GBN, M_IDS / GBM);   // (3, 512), n-tiles fastest
    gemm_tc_kernel<<<grid, 256, SMEM_TOTAL>>>(b, C);
}

// round 13
// speedup vs baseline: 1.9846x; 1.1442x over previous
#include <cuda_runtime.h>
#include <cuda_bf16.h>
#include <cstdint>

#define M_IDS   65536
#define N_HID   768
#define K_FEAT  220
#define KP      256
#define NDOCS   128
#define NQUER   2000

#define GBM 128
#define GBN 256
#define KC  64
#define NCH (KP / KC)            // 4
#define NTM (M_IDS / GBM)        // 512 m-tiles
#define NTN (N_HID / GBN)        // 3 n-tiles
#define ABLK 16384               // A plane block: 128 rows x 128B (swizzled image)
#define BBLK 32768               // B plane block: 256 rows x 128B (swizzled image)

// ---------------- scratch (__device__ globals; no allocation allowed) -------
// Tiled, pre-swizzled smem images: [tile][chunk][plane] blocks.
__device__ uint4 g_Atiles[(size_t)NTM * NCH * 2 * (ABLK / 16)];   // 64 MB
__device__ uint4 g_Btiles[(size_t)NTN * NCH * 2 * (BBLK / 16)];   // 768 KB
__device__ int g_ids_is_i32;

// tcgen05 is arch-accelerated: only in the sm_103a pass, not compute_103 PTX.
#if defined(__CUDA_ARCH__) && defined(__CUDA_ARCH_FEAT_SM103_ALL)
#define HAS_TCGEN05 1
#else
#define HAS_TCGEN05 0
#endif

__device__ __forceinline__ uint32_t smem_u32(const void* p) {
    uint32_t a;
    asm("{ .reg .u64 t; cvta.to.shared.u64 t, %1; cvt.u32.u64 %0, t; }" : "=r"(a) : "l"(p));
    return a;
}

#if HAS_TCGEN05

#define MBAR_INIT(addr, cnt) \
    asm volatile("mbarrier.init.shared.b64 [%0], %1;" :: "r"(addr), "r"(cnt) : "memory")

#define MBAR_WAIT(addr, par) do {                                              \
    uint32_t _m = (addr); uint32_t _p = (par); uint32_t _done;                 \
    asm volatile("{\n\t.reg .pred p;\n\t"                                      \
        "mbarrier.try_wait.parity.acquire.cta.shared::cta.b64 p, [%1], %2;\n\t"\
        "selp.b32 %0, 1, 0, p;\n\t}"                                           \
        : "=r"(_done) : "r"(_m), "r"(_p) : "memory");                          \
    if (!_done) {                                                              \
        asm volatile("{\n\t.reg .pred P1;\n\t"                                 \
            "W_%=:\n\t"                                                        \
            "mbarrier.try_wait.parity.acquire.cta.shared::cta.b64 P1, [%0], %1, 0x989680;\n\t" \
            "@P1 bra.uni D_%=;\n\t"                                            \
            "bra.uni W_%=;\n\t"                                                \
            "D_%=:\n\t}" :: "r"(_m), "r"(_p) : "memory");                      \
    }                                                                          \
} while (0)

// 16B async copy, L1-bypass; completion via commit_group/wait_group
#define CP16(dst, src) \
    asm volatile("cp.async.cg.shared.global [%0], [%1], 16;" :: "r"(dst), "l"(src) : "memory")
#define CP_COMMIT() asm volatile("cp.async.commit_group;" ::: "memory")
#define CP_WAIT(n)  asm volatile("cp.async.wait_group %0;" :: "n"(n) : "memory")

// 64-bit SMEM descriptor: SW128, version=1 (Blackwell), LBO=1, SBO=64
__device__ __forceinline__ uint64_t make_desc_sw128(uint32_t addr) {
    const uint64_t base = (uint64_t(2) << 61) | (uint64_t(1) << 46)
                        | (uint64_t(64) << 32) | (uint64_t(1) << 16);
    return base | ((uint64_t)(addr >> 4) & 0x3FFF);
}

__device__ __forceinline__ void mma_f16_ss(uint32_t d_tmem, uint64_t a_desc,
                                           uint64_t b_desc, uint32_t idesc,
                                           uint32_t enable) {
    asm volatile(
        "{\n\t.reg .pred p;\n\t"
        "setp.ne.u32 p, %5, 0;\n\t"
        "tcgen05.mma.cta_group::1.kind::f16 [%0], %1, %2, %3, {%4, %4, %4, %4}, p;\n\t"
        "}"
        :: "r"(d_tmem), "l"(a_desc), "l"(b_desc), "r"(idesc), "r"(0u), "r"(enable)
        : "memory");
}

#define TC_COMMIT(mbar) \
    asm volatile("tcgen05.commit.cta_group::1.mbarrier::arrive::one.shared::cluster.b64 [%0];" \
                 :: "r"(mbar) : "memory")
#define TC_ALLOC(smem_res, n) \
    asm volatile("tcgen05.alloc.cta_group::1.sync.aligned.shared::cta.b32 [%0], %1;" \
                 :: "r"(smem_res), "r"(n) : "memory")
#define TC_RELINQ() \
    asm volatile("tcgen05.relinquish_alloc_permit.cta_group::1.sync.aligned;")
#define TC_DEALLOC(tmem, n) \
    asm volatile("tcgen05.dealloc.cta_group::1.sync.aligned.b32 %0, %1;" :: "r"(tmem), "r"(n))
#define TC_FENCE_AFTER()  asm volatile("tcgen05.fence::after_thread_sync;" ::: "memory")
#define TC_FENCE_BEFORE() asm volatile("tcgen05.fence::before_thread_sync;" ::: "memory")
#define TC_WAIT_LD()      asm volatile("tcgen05.wait::ld.sync.aligned;" ::: "memory")

#define TC_LD_X32(r, addr)                                                     \
    asm volatile("tcgen05.ld.sync.aligned.32x32b.x32.b32 "                     \
        "{%0,%1,%2,%3,%4,%5,%6,%7,%8,%9,%10,%11,%12,%13,%14,%15,"              \
        "%16,%17,%18,%19,%20,%21,%22,%23,%24,%25,%26,%27,%28,%29,%30,%31}, [%32];" \
        : "=r"((r)[0]),"=r"((r)[1]),"=r"((r)[2]),"=r"((r)[3]),                 \
          "=r"((r)[4]),"=r"((r)[5]),"=r"((r)[6]),"=r"((r)[7]),                 \
          "=r"((r)[8]),"=r"((r)[9]),"=r"((r)[10]),"=r"((r)[11]),               \
          "=r"((r)[12]),"=r"((r)[13]),"=r"((r)[14]),"=r"((r)[15]),             \
          "=r"((r)[16]),"=r"((r)[17]),"=r"((r)[18]),"=r"((r)[19]),             \
          "=r"((r)[20]),"=r"((r)[21]),"=r"((r)[22]),"=r"((r)[23]),             \
          "=r"((r)[24]),"=r"((r)[25]),"=r"((r)[26]),"=r"((r)[27]),             \
          "=r"((r)[28]),"=r"((r)[29]),"=r"((r)[30]),"=r"((r)[31])              \
        : "r"(addr))

#endif  // HAS_TCGEN05

// ---------------------------------------------------------------------------
// Kernel 0: ids layout detection (int64 LE vs int32 pairs)
// ---------------------------------------------------------------------------
__global__ void detect_ids_kernel(const int* __restrict__ w) {
    int any = 0;
    for (int i = threadIdx.x; i < 2048; i += 32) any |= w[2 * i + 1];
    any = __reduce_or_sync(0xffffffffu, any);
    if (threadIdx.x == 0) g_ids_is_i32 = (any != 0) ? 1 : 0;
}

// ---------------------------------------------------------------------------
// hi/lo split helpers
// ---------------------------------------------------------------------------
__device__ __forceinline__ uint32_t pack2bf(float a, float b) {
    __nv_bfloat162 t = __floats2bfloat162_rn(a, b);
    return *(uint32_t*)&t;
}

__device__ __forceinline__ void split8(const float4& v0, const float4& v1,
                                       uint4& hi, uint4& lo) {
    __nv_bfloat16 h[8];
    float f[8] = { v0.x, v0.y, v0.z, v0.w, v1.x, v1.y, v1.z, v1.w };
    float l[8];
#pragma unroll
    for (int i = 0; i < 8; i++) {
        h[i] = __float2bfloat16(f[i]);
        l[i] = f[i] - __bfloat162float(h[i]);
    }
    hi.x = pack2bf(__bfloat162float(h[0]), __bfloat162float(h[1]));
    hi.y = pack2bf(__bfloat162float(h[2]), __bfloat162float(h[3]));
    hi.z = pack2bf(__bfloat162float(h[4]), __bfloat162float(h[5]));
    hi.w = pack2bf(__bfloat162float(h[6]), __bfloat162float(h[7]));
    lo.x = pack2bf(l[0], l[1]);
    lo.y = pack2bf(l[2], l[3]);
    lo.z = pack2bf(l[4], l[5]);
    lo.w = pack2bf(l[6], l[7]);
}

// ---------------------------------------------------------------------------
// Kernel 1: W -> tiled swizzled bf16 hi/lo block images
// ---------------------------------------------------------------------------
__global__ __launch_bounds__(256)
void wprep_kernel(const float* __restrict__ W) {
    int row = blockIdx.x * 8 + (threadIdx.x >> 5);
    int j   = threadIdx.x & 31;
    const float4* src = (const float4*)(W + (size_t)row * K_FEAT);
    float4 z = make_float4(0.f, 0.f, 0.f, 0.f);
    float4 x0 = (8 * j + 3 < K_FEAT) ? src[2 * j]     : z;
    float4 x1 = (8 * j + 7 < K_FEAT) ? src[2 * j + 1] : z;
    uint4 hi, lo;
    split8(x0, x1, hi, lo);

    int tn = row >> 8, rn = row & 255;
    int c = j >> 3, uc = j & 7;
    uint32_t off = (uint32_t)(rn * 128 + uc * 16);
    uint32_t swz = off ^ ((off >> 3) & 0x70);
    size_t base = ((((size_t)tn * NCH + c) * 2) * BBLK + swz) >> 4;
    g_Btiles[base] = hi;
    g_Btiles[base + BBLK / 16] = lo;
}

// ---------------------------------------------------------------------------
// Kernel 2: gather + log1p(|x|)*sign(x) -> fb + tiled swizzled hi/lo images
// ---------------------------------------------------------------------------
__global__ __launch_bounds__(256)
void gather_transform_kernel(const int* __restrict__ ids32,
                             const float* __restrict__ table,
                             float* __restrict__ fb, int write_fb) {
    int r = blockIdx.x * 8 + (threadIdx.x >> 5);
    int j = threadIdx.x & 31;
    int q, d;
    if (g_ids_is_i32) { q = ids32[2 * r]; d = ids32[2 * r + 1]; }
    else              { q = ids32[4 * r]; d = ids32[4 * r + 2]; }
    q = min(max(q, 0), NQUER - 1);
    d = min(max(d, 0), NDOCS - 1);
    const float4* src = (const float4*)(table + ((size_t)q * NDOCS + d) * K_FEAT);

    float4 z = make_float4(0.f, 0.f, 0.f, 0.f);
    bool v0ok = (8 * j + 3 < K_FEAT), v1ok = (8 * j + 7 < K_FEAT);
    float4 x0 = v0ok ? src[2 * j]     : z;
    float4 x1 = v1ok ? src[2 * j + 1] : z;
    float4 v0, v1;
    v0.x = copysignf(__logf(fabsf(x0.x) + 1.0f), x0.x);
    v0.y = copysignf(__logf(fabsf(x0.y) + 1.0f), x0.y);
    v0.z = copysignf(__logf(fabsf(x0.z) + 1.0f), x0.z);
    v0.w = copysignf(__logf(fabsf(x0.w) + 1.0f), x0.w);
    v1.x = copysignf(__logf(fabsf(x1.x) + 1.0f), x1.x);
    v1.y = copysignf(__logf(fabsf(x1.y) + 1.0f), x1.y);
    v1.z = copysignf(__logf(fabsf(x1.z) + 1.0f), x1.z);
    v1.w = copysignf(__logf(fabsf(x1.w) + 1.0f), x1.w);
    if (write_fb) {
        if (v0ok) *(float4*)&fb[(size_t)r * K_FEAT + 8 * j]     = v0;
        if (v1ok) *(float4*)&fb[(size_t)r * K_FEAT + 8 * j + 4] = v1;
    }

    uint4 hi, lo;
    split8(v0, v1, hi, lo);

    int tm = r >> 7, ri = r & 127;
    int c = j >> 3, uc = j & 7;
    uint32_t off = (uint32_t)(ri * 128 + uc * 16);
    uint32_t swz = off ^ ((off >> 3) & 0x70);
    size_t base = ((((size_t)tm * NCH + c) * 2) * ABLK + swz) >> 4;
    g_Atiles[base] = hi;
    g_Atiles[base + ABLK / 16] = lo;
}

// ---------------------------------------------------------------------------
// Kernel 3: tcgen05 GEMM, cp.async(LDGSTS) fed, 2-stage, TMEM accumulator
// ---------------------------------------------------------------------------
#define ST_A ABLK                // 16 KB
#define ST_B BBLK                // 32 KB
#define STAGE (2*ST_A + 2*ST_B)  // 98304
#define AUX (2 * STAGE)          // 196608
#define OFF_TMEMPTR (AUX + 0)
#define OFF_MMAD    (AUX + 8)    // mmad[0]=+8, mmad[1]=+16
#define OFF_BIAS    (AUX + 128)
#define SMEM_TOTAL  (AUX + 128 + GBN * 4)

static constexpr uint32_t IDESC =
    (1u << 4) | (1u << 7) | (1u << 10) | ((GBN / 8) << 17) | ((GBM / 16) << 24);

#if HAS_TCGEN05
// Copy one chunk's pre-swizzled images into stage smem (all 256 threads).
__device__ __forceinline__ void fill_stage(uint32_t sbase, const char* Abase,
                                           const char* Bbase, int c, int tid) {
    const char* As = Abase + (size_t)(c * 2) * ABLK;
#pragma unroll
    for (int k = 0; k < 8; k++) {
        int i = tid + k * 256;              // 0..2047
        int pl = i >> 10, w = i & 1023;
        CP16(sbase + pl * ST_A + w * 16, As + (size_t)pl * ABLK + (size_t)w * 16);
    }
    const char* Bs = Bbase + (size_t)(c * 2) * BBLK;
#pragma unroll
    for (int k = 0; k < 16; k++) {
        int i = tid + k * 256;              // 0..4095
        int pl = i >> 11, w = i & 2047;
        CP16(sbase + 2 * ST_A + pl * ST_B + w * 16, Bs + (size_t)pl * BBLK + (size_t)w * 16);
    }
}
#endif

__global__ __launch_bounds__(256, 1)
void gemm_tc_kernel(const float* __restrict__ bias, float* __restrict__ C) {
#if HAS_TCGEN05
    extern __shared__ char sm[];
    const uint32_t sb = smem_u32(sm);
    const int tid = threadIdx.x;
    const int warp = tid >> 5, lane = tid & 31;
    const int n0 = blockIdx.x * GBN;
    const int m0 = blockIdx.y * GBM;

    if (warp == 0) {
        TC_ALLOC(sb + OFF_TMEMPTR, 256);
        TC_RELINQ();
    }
    if (tid == 0) {
        MBAR_INIT(sb + OFF_MMAD + 0, 1);
        MBAR_INIT(sb + OFF_MMAD + 8, 1);
        asm volatile("fence.proxy.async.shared::cta;" ::: "memory");
    }
    ((float*)(sm + OFF_BIAS))[tid] = bias[n0 + tid];
    __syncthreads();
    uint32_t tmem;
    asm volatile("ld.shared.b32 %0, [%1];" : "=r"(tmem) : "r"(sb + OFF_TMEMPTR));

    const char* Abase = (const char*)(g_Atiles + (size_t)blockIdx.y * (NCH * 2 * (ABLK / 16)));
    const char* Bbase = (const char*)(g_Btiles + (size_t)blockIdx.x * (NCH * 2 * (BBLK / 16)));

    // ---- prologue: fill both stages ----
    fill_stage(sb + 0 * STAGE, Abase, Bbase, 0, tid); CP_COMMIT();
    fill_stage(sb + 1 * STAGE, Abase, Bbase, 1, tid); CP_COMMIT();

    // ---- mainloop ----
#pragma unroll
    for (int c = 0; c < NCH; c++) {
        const int s = c & 1;
        if (c < NCH - 1) { CP_WAIT(1); } else { CP_WAIT(0); }
        __syncthreads();                     // all threads' chunk-c copies done
        if (tid == 0) {
            asm volatile("fence.proxy.async.shared::cta;" ::: "memory");
            uint64_t dA[2] = { make_desc_sw128(sb + s * STAGE),
                               make_desc_sw128(sb + s * STAGE + ST_A) };
            uint64_t dB[2] = { make_desc_sw128(sb + s * STAGE + 2 * ST_A),
                               make_desc_sw128(sb + s * STAGE + 2 * ST_A + ST_B) };
#pragma unroll
            for (int p = 0; p < 3; p++) {
                uint64_t ad = dA[p == 2 ? 1 : 0];
                uint64_t bd = dB[p == 1 ? 1 : 0];
#pragma unroll
                for (int k = 0; k < 4; k++) {
                    uint32_t en = (c == 0 && p == 0 && k == 0) ? 0u : 1u;
                    mma_f16_ss(tmem, ad + 2 * k, bd + 2 * k, IDESC, en);
                }
            }
            TC_COMMIT(sb + OFF_MMAD + s * 8);
        }
        if (c + 2 < NCH) {
            // stage s reusable once chunk c's MMAs complete (commit c -> parity 0)
            MBAR_WAIT(sb + OFF_MMAD + s * 8, 0);
            fill_stage(sb + s * STAGE, Abase, Bbase, c + 2, tid);
            CP_COMMIT();
        }
    }

    // all threads: wait last chunk's MMAs (mmad[1]: c=1 -> p0, c=3 -> p1)
    MBAR_WAIT(sb + OFF_MMAD + 8, 1);
    TC_FENCE_AFTER();

    // epilogue: warps 0-3 -> cols 0..127, warps 4-7 -> cols 128..255
    const int half = warp >> 2;
    const int mrow = m0 + (warp & 3) * 32 + lane;
    const float* bs = (const float*)(sm + OFF_BIAS);
#pragma unroll
    for (int p = 0; p < 4; p++) {
        const int cb = half * 128 + p * 32;
        uint32_t r[32];
        TC_LD_X32(r, tmem + cb);
        TC_WAIT_LD();
        float o[32];
#pragma unroll
        for (int cc = 0; cc < 32; cc++)
            o[cc] = fmaxf(__uint_as_float(r[cc]) + bs[cb + cc], 0.0f);
        float* dst = &C[(size_t)mrow * N_HID + n0 + cb];
#pragma unroll
        for (int v4 = 0; v4 < 8; v4++) {
            float4 t = make_float4(o[v4 * 4], o[v4 * 4 + 1], o[v4 * 4 + 2], o[v4 * 4 + 3]);
            *(float4*)&dst[v4 * 4] = t;
        }
    }
    TC_FENCE_BEFORE();
    __syncthreads();
    if (warp == 0) TC_DEALLOC(tmem, 256);
#else
    // Portable-PTX fallback (never used when the sm_103a cubin loads). Slow but correct.
    const int tid = threadIdx.x;
    const int n0 = blockIdx.x * GBN, m0 = blockIdx.y * GBM;
    for (int idx = tid; idx < GBM * GBN; idx += blockDim.x) {
        int mi = idx / GBN, ni = idx - mi * GBN;
        int tm = (m0 + mi) >> 7, rim = (m0 + mi) & 127;
        int tn = (n0 + ni) >> 8, rin = (n0 + ni) & 255;
        float acc = 0.0f;
        for (int k = 0; k < KP; k++) {
            int c = k >> 6, kk = k & 63, uc = kk >> 3, e = kk & 7;
            uint32_t offa = (uint32_t)(rim * 128 + uc * 16);
            offa = (offa ^ ((offa >> 3) & 0x70)) + e * 2;
            uint32_t offb = (uint32_t)(rin * 128 + uc * 16);
            offb = (offb ^ ((offb >> 3) & 0x70)) + e * 2;
            const __nv_bfloat16* Ah = (const __nv_bfloat16*)((const char*)g_Atiles +
                (((size_t)tm * NCH + c) * 2) * ABLK + offa);
            const __nv_bfloat16* Al = (const __nv_bfloat16*)((const char*)Ah + ABLK);
            const __nv_bfloat16* Bh = (const __nv_bfloat16*)((const char*)g_Btiles +
                (((size_t)tn * NCH + c) * 2) * BBLK + offb);
            const __nv_bfloat16* Bl = (const __nv_bfloat16*)((const char*)Bh + BBLK);
            float a = __bfloat162float(*Ah) + __bfloat162float(*Al);
            float w = __bfloat162float(*Bh) + __bfloat162float(*Bl);
            acc += a * w;
        }
        C[(size_t)(m0 + mi) * N_HID + n0 + ni] = fmaxf(acc + bias[n0 + ni], 0.0f);
    }
#endif
}

// ---------------------------------------------------------------------------
extern "C" void kernel_launch(void* const* d_in, const int* in_sizes, int n_in,
                              void* d_out, int out_size) {
    const int*   ids32 = nullptr;
    const float* table = nullptr;
    const float* W     = nullptr;
    const float* b     = nullptr;
    for (int i = 0; i < n_in; i++) {
        if (in_sizes[i] == M_IDS * 2)                   ids32 = (const int*)d_in[i];
        else if (in_sizes[i] == NQUER * NDOCS * K_FEAT) table = (const float*)d_in[i];
        else if (in_sizes[i] == N_HID * K_FEAT)         W     = (const float*)d_in[i];
        else if (in_sizes[i] == N_HID)                  b     = (const float*)d_in[i];
    }

    float* out    = (float*)d_out;
    float* C      = out;                               // [65536, 768]
    float* fb_out = out + (size_t)M_IDS * N_HID;       // [65536, 220]
    int write_fb  = (out_size >= M_IDS * (N_HID + K_FEAT)) ? 1 : 0;

    cudaFuncSetAttribute(gemm_tc_kernel,
                         cudaFuncAttributeMaxDynamicSharedMemorySize, SMEM_TOTAL);

    detect_ids_kernel<<<1, 32>>>(ids32);
    wprep_kernel<<<N_HID / 8, 256>>>(W);
    gather_transform_kernel<<<M_IDS / 8, 256>>>(ids32, table, fb_out, write_fb);

    dim3 grid(NTN, NTM);   // (3, 512), n-tiles fastest
    gemm_tc_kernel<<<grid, 256, SMEM_TOTAL>>>(b, C);
}

// round 16
// speedup vs baseline: 2.0305x; 1.0232x over previous
#include <cuda_runtime.h>
#include <cuda_bf16.h>
#include <cstdint>

#define M_IDS   65536
#define N_HID   768
#define K_FEAT  220
#define KP      256
#define NDOCS   128
#define NQUER   2000

#define GBM 128
#define GBN 256
#define KC  64
#define NCH (KP / KC)            // 4
#define NTM (M_IDS / GBM)        // 512 m-tiles
#define NTN (N_HID / GBN)        // 3 n-tiles
#define NTILES (NTM * NTN)       // 1536
#define NSM 148
#define ABLK 16384               // A plane block: 128 rows x 128B (swizzled image)
#define BBLK 32768               // B plane block: 256 rows x 128B (swizzled image)

// ---------------- scratch (__device__ globals; no allocation allowed) -------
__device__ uint4 g_Atiles[(size_t)NTM * NCH * 2 * (ABLK / 16)];   // 64 MB
__device__ uint4 g_Btiles[(size_t)NTN * NCH * 2 * (BBLK / 16)];   // 768 KB
__device__ int g_ids_is_i32;

// tcgen05 is arch-accelerated: only in the sm_103a pass, not compute_103 PTX.
#if defined(__CUDA_ARCH__) && defined(__CUDA_ARCH_FEAT_SM103_ALL)
#define HAS_TCGEN05 1
#else
#define HAS_TCGEN05 0
#endif

__device__ __forceinline__ uint32_t smem_u32(const void* p) {
    uint32_t a;
    asm("{ .reg .u64 t; cvta.to.shared.u64 t, %1; cvt.u32.u64 %0, t; }" : "=r"(a) : "l"(p));
    return a;
}

#if HAS_TCGEN05

#define MBAR_INIT(addr, cnt) \
    asm volatile("mbarrier.init.shared.b64 [%0], %1;" :: "r"(addr), "r"(cnt) : "memory")

#define MBAR_WAIT(addr, par) do {                                              \
    uint32_t _m = (addr); uint32_t _p = (par); uint32_t _done;                 \
    asm volatile("{\n\t.reg .pred p;\n\t"                                      \
        "mbarrier.try_wait.parity.acquire.cta.shared::cta.b64 p, [%1], %2;\n\t"\
        "selp.b32 %0, 1, 0, p;\n\t}"                                           \
        : "=r"(_done) : "r"(_m), "r"(_p) : "memory");                          \
    if (!_done) {                                                              \
        asm volatile("{\n\t.reg .pred P1;\n\t"                                 \
            "W_%=:\n\t"                                                        \
            "mbarrier.try_wait.parity.acquire.cta.shared::cta.b64 P1, [%0], %1, 0x989680;\n\t" \
            "@P1 bra.uni D_%=;\n\t"                                            \
            "bra.uni W_%=;\n\t"                                                \
            "D_%=:\n\t}" :: "r"(_m), "r"(_p) : "memory");                      \
    }                                                                          \
} while (0)

// 16B async copy, L1-bypass; completion via commit_group/wait_group
#define CP16(dst, src) \
    asm volatile("cp.async.cg.shared.global [%0], [%1], 16;" :: "r"(dst), "l"(src) : "memory")
#define CP_COMMIT() asm volatile("cp.async.commit_group;" ::: "memory")
#define CP_WAIT(n)  asm volatile("cp.async.wait_group %0;" :: "n"(n) : "memory")

// 64-bit SMEM descriptor: SW128, version=1 (Blackwell), LBO=1, SBO=64
__device__ __forceinline__ uint64_t make_desc_sw128(uint32_t addr) {
    const uint64_t base = (uint64_t(2) << 61) | (uint64_t(1) << 46)
                        | (uint64_t(64) << 32) | (uint64_t(1) << 16);
    return base | ((uint64_t)(addr >> 4) & 0x3FFF);
}

__device__ __forceinline__ void mma_f16_ss(uint32_t d_tmem, uint64_t a_desc,
                                           uint64_t b_desc, uint32_t idesc,
                                           uint32_t enable) {
    asm volatile(
        "{\n\t.reg .pred p;\n\t"
        "setp.ne.u32 p, %5, 0;\n\t"
        "tcgen05.mma.cta_group::1.kind::f16 [%0], %1, %2, %3, {%4, %4, %4, %4}, p;\n\t"
        "}"
        :: "r"(d_tmem), "l"(a_desc), "l"(b_desc), "r"(idesc), "r"(0u), "r"(enable)
        : "memory");
}

#define TC_COMMIT(mbar) \
    asm volatile("tcgen05.commit.cta_group::1.mbarrier::arrive::one.shared::cluster.b64 [%0];" \
                 :: "r"(mbar) : "memory")
#define TC_ALLOC(smem_res, n) \
    asm volatile("tcgen05.alloc.cta_group::1.sync.aligned.shared::cta.b32 [%0], %1;" \
                 :: "r"(smem_res), "r"(n) : "memory")
#define TC_RELINQ() \
    asm volatile("tcgen05.relinquish_alloc_permit.cta_group::1.sync.aligned;")
#define TC_DEALLOC(tmem, n) \
    asm volatile("tcgen05.dealloc.cta_group::1.sync.aligned.b32 %0, %1;" :: "r"(tmem), "r"(n))
#define TC_FENCE_AFTER()  asm volatile("tcgen05.fence::after_thread_sync;" ::: "memory")
#define TC_FENCE_BEFORE() asm volatile("tcgen05.fence::before_thread_sync;" ::: "memory")
#define TC_WAIT_LD()      asm volatile("tcgen05.wait::ld.sync.aligned;" ::: "memory")

#define TC_LD_X32(r, addr)                                                     \
    asm volatile("tcgen05.ld.sync.aligned.32x32b.x32.b32 "                     \
        "{%0,%1,%2,%3,%4,%5,%6,%7,%8,%9,%10,%11,%12,%13,%14,%15,"              \
        "%16,%17,%18,%19,%20,%21,%22,%23,%24,%25,%26,%27,%28,%29,%30,%31}, [%32];" \
        : "=r"((r)[0]),"=r"((r)[1]),"=r"((r)[2]),"=r"((r)[3]),                 \
          "=r"((r)[4]),"=r"((r)[5]),"=r"((r)[6]),"=r"((r)[7]),                 \
          "=r"((r)[8]),"=r"((r)[9]),"=r"((r)[10]),"=r"((r)[11]),               \
          "=r"((r)[12]),"=r"((r)[13]),"=r"((r)[14]),"=r"((r)[15]),             \
          "=r"((r)[16]),"=r"((r)[17]),"=r"((r)[18]),"=r"((r)[19]),             \
          "=r"((r)[20]),"=r"((r)[21]),"=r"((r)[22]),"=r"((r)[23]),             \
          "=r"((r)[24]),"=r"((r)[25]),"=r"((r)[26]),"=r"((r)[27]),             \
          "=r"((r)[28]),"=r"((r)[29]),"=r"((r)[30]),"=r"((r)[31])              \
        : "r"(addr))

#endif  // HAS_TCGEN05

// ---------------------------------------------------------------------------
// Kernel 0: ids layout detection (int64 LE vs int32 pairs)
// ---------------------------------------------------------------------------
__global__ void detect_ids_kernel(const int* __restrict__ w) {
    int any = 0;
    for (int i = threadIdx.x; i < 2048; i += 32) any |= w[2 * i + 1];
    any = __reduce_or_sync(0xffffffffu, any);
    if (threadIdx.x == 0) g_ids_is_i32 = (any != 0) ? 1 : 0;
}

// ---------------------------------------------------------------------------
// hi/lo split helpers
// ---------------------------------------------------------------------------
__device__ __forceinline__ uint32_t pack2bf(float a, float b) {
    __nv_bfloat162 t = __floats2bfloat162_rn(a, b);
    return *(uint32_t*)&t;
}

__device__ __forceinline__ void split8(const float4& v0, const float4& v1,
                                       uint4& hi, uint4& lo) {
    __nv_bfloat16 h[8];
    float f[8] = { v0.x, v0.y, v0.z, v0.w, v1.x, v1.y, v1.z, v1.w };
    float l[8];
#pragma unroll
    for (int i = 0; i < 8; i++) {
        h[i] = __float2bfloat16(f[i]);
        l[i] = f[i] - __bfloat162float(h[i]);
    }
    hi.x = pack2bf(__bfloat162float(h[0]), __bfloat162float(h[1]));
    hi.y = pack2bf(__bfloat162float(h[2]), __bfloat162float(h[3]));
    hi.z = pack2bf(__bfloat162float(h[4]), __bfloat162float(h[5]));
    hi.w = pack2bf(__bfloat162float(h[6]), __bfloat162float(h[7]));
    lo.x = pack2bf(l[0], l[1]);
    lo.y = pack2bf(l[2], l[3]);
    lo.z = pack2bf(l[4], l[5]);
    lo.w = pack2bf(l[6], l[7]);
}

// ---------------------------------------------------------------------------
// Kernel 1: W -> tiled swizzled bf16 hi/lo block images
// ---------------------------------------------------------------------------
__global__ __launch_bounds__(256)
void wprep_kernel(const float* __restrict__ W) {
    int row = blockIdx.x * 8 + (threadIdx.x >> 5);
    int j   = threadIdx.x & 31;
    const float4* src = (const float4*)(W + (size_t)row * K_FEAT);
    float4 z = make_float4(0.f, 0.f, 0.f, 0.f);
    float4 x0 = (8 * j + 3 < K_FEAT) ? src[2 * j]     : z;
    float4 x1 = (8 * j + 7 < K_FEAT) ? src[2 * j + 1] : z;
    uint4 hi, lo;
    split8(x0, x1, hi, lo);

    int tn = row >> 8, rn = row & 255;
    int c = j >> 3, uc = j & 7;
    uint32_t off = (uint32_t)(rn * 128 + uc * 16);
    uint32_t swz = off ^ ((off >> 3) & 0x70);
    size_t base = ((((size_t)tn * NCH + c) * 2) * BBLK + swz) >> 4;
    g_Btiles[base] = hi;
    g_Btiles[base + BBLK / 16] = lo;
}

// ---------------------------------------------------------------------------
// Kernel 2: gather + log1p(|x|)*sign(x) -> fb + tiled swizzled hi/lo images
// ---------------------------------------------------------------------------
__global__ __launch_bounds__(256)
void gather_transform_kernel(const int* __restrict__ ids32,
                             const float* __restrict__ table,
                             float* __restrict__ fb, int write_fb) {
    int r = blockIdx.x * 8 + (threadIdx.x >> 5);
    int j = threadIdx.x & 31;
    int q, d;
    if (g_ids_is_i32) { q = ids32[2 * r]; d = ids32[2 * r + 1]; }
    else              { q = ids32[4 * r]; d = ids32[4 * r + 2]; }
    q = min(max(q, 0), NQUER - 1);
    d = min(max(d, 0), NDOCS - 1);
    const float4* src = (const float4*)(table + ((size_t)q * NDOCS + d) * K_FEAT);

    float4 z = make_float4(0.f, 0.f, 0.f, 0.f);
    bool v0ok = (8 * j + 3 < K_FEAT), v1ok = (8 * j + 7 < K_FEAT);
    float4 x0 = v0ok ? src[2 * j]     : z;
    float4 x1 = v1ok ? src[2 * j + 1] : z;
    float4 v0, v1;
    v0.x = copysignf(__logf(fabsf(x0.x) + 1.0f), x0.x);
    v0.y = copysignf(__logf(fabsf(x0.y) + 1.0f), x0.y);
    v0.z = copysignf(__logf(fabsf(x0.z) + 1.0f), x0.z);
    v0.w = copysignf(__logf(fabsf(x0.w) + 1.0f), x0.w);
    v1.x = copysignf(__logf(fabsf(x1.x) + 1.0f), x1.x);
    v1.y = copysignf(__logf(fabsf(x1.y) + 1.0f), x1.y);
    v1.z = copysignf(__logf(fabsf(x1.z) + 1.0f), x1.z);
    v1.w = copysignf(__logf(fabsf(x1.w) + 1.0f), x1.w);
    if (write_fb) {
        if (v0ok) *(float4*)&fb[(size_t)r * K_FEAT + 8 * j]     = v0;
        if (v1ok) *(float4*)&fb[(size_t)r * K_FEAT + 8 * j + 4] = v1;
    }

    uint4 hi, lo;
    split8(v0, v1, hi, lo);

    int tm = r >> 7, ri = r & 127;
    int c = j >> 3, uc = j & 7;
    uint32_t off = (uint32_t)(ri * 128 + uc * 16);
    uint32_t swz = off ^ ((off >> 3) & 0x70);
    size_t base = ((((size_t)tm * NCH + c) * 2) * ABLK + swz) >> 4;
    g_Atiles[base] = hi;
    g_Atiles[base + ABLK / 16] = lo;
}

// ---------------------------------------------------------------------------
// Kernel 3: persistent tcgen05 GEMM, cp.async fed, TMEM double-buffer
// ---------------------------------------------------------------------------
#define ST_A ABLK                // 16 KB
#define ST_B BBLK                // 32 KB
#define STAGE (2*ST_A + 2*ST_B)  // 98304
#define AUX (2 * STAGE)          // 196608
#define OFF_TMEMPTR (AUX + 0)
#define OFF_MMAD    (AUX + 8)    // mmad[0]=+8, mmad[1]=+16
#define OFF_TCMP    (AUX + 24)   // tilecomp[0]=+24, tilecomp[1]=+32
#define OFF_BIAS    (AUX + 128)
#define SMEM_TOTAL  (AUX + 128 + N_HID * 4)

static constexpr uint32_t IDESC =
    (1u << 4) | (1u << 7) | (1u << 10) | ((GBN / 8) << 17) | ((GBM / 16) << 24);

#if HAS_TCGEN05
// Copy chunk gi's pre-swizzled images into its stage (all 256 threads).
__device__ __forceinline__ void fill_chunk(uint32_t sb, int gi, int bid, int tid) {
    const int tau = bid + (gi >> 2) * NSM;
    const int c   = gi & 3;
    const uint32_t sbase = sb + (gi & 1) * STAGE;
    const char* As = (const char*)g_Atiles + ((size_t)(tau / NTN) * (NCH * 2) + c * 2) * ABLK;
    const char* Bs = (const char*)g_Btiles + ((size_t)(tau % NTN) * (NCH * 2) + c * 2) * BBLK;
#pragma unroll
    for (int k = 0; k < 8; k++) {
        int i = tid + k * 256;              // 0..2047
        int pl = i >> 10, w = i & 1023;
        CP16(sbase + pl * ST_A + w * 16, As + (size_t)pl * ABLK + (size_t)w * 16);
    }
#pragma unroll
    for (int k = 0; k < 16; k++) {
        int i = tid + k * 256;              // 0..4095
        int pl = i >> 11, w = i & 2047;
        CP16(sbase + 2 * ST_A + pl * ST_B + w * 16, Bs + (size_t)pl * BBLK + (size_t)w * 16);
    }
}

// Epilogue for local tile t: wait tilecomp[t&1], LDTM + bias + relu + store.
__device__ __forceinline__ void epilogue_tile(const char* smc, uint32_t sb, uint32_t tmem,
                                              float* C, int t, int bid,
                                              int warp, int lane) {
    const int tau = bid + t * NSM;
    const int n0  = (tau % NTN) * GBN;
    const int m0  = (tau / NTN) * GBM;
    MBAR_WAIT(sb + OFF_TCMP + (t & 1) * 8, (t >> 1) & 1);
    TC_FENCE_AFTER();
    const uint32_t acc = tmem + (uint32_t)((t & 1) * 256);
    const int halfw = warp >> 2;
    const int mrow = m0 + (warp & 3) * 32 + lane;
    const float* bs = (const float*)(smc + OFF_BIAS) + n0;
#pragma unroll
    for (int p = 0; p < 4; p++) {
        const int cb = halfw * 128 + p * 32;
        uint32_t r[32];
        TC_LD_X32(r, acc + cb);
        TC_WAIT_LD();
        float o[32];
#pragma unroll
        for (int cc = 0; cc < 32; cc++)
            o[cc] = fmaxf(__uint_as_float(r[cc]) + bs[cb + cc], 0.0f);
        float* dst = &C[(size_t)mrow * N_HID + n0 + cb];
#pragma unroll
        for (int v4 = 0; v4 < 8; v4++) {
            float4 tv = make_float4(o[v4 * 4], o[v4 * 4 + 1], o[v4 * 4 + 2], o[v4 * 4 + 3]);
            *(float4*)&dst[v4 * 4] = tv;
        }
    }
    TC_FENCE_BEFORE();
}
#endif

__global__ __launch_bounds__(256, 1)
void gemm_tc_kernel(const float* __restrict__ bias, float* __restrict__ C) {
#if HAS_TCGEN05
    extern __shared__ char sm[];
    const uint32_t sb = smem_u32(sm);
    const int tid = threadIdx.x;
    const int warp = tid >> 5, lane = tid & 31;
    const int bid = blockIdx.x;

    if (warp == 0) {
        TC_ALLOC(sb + OFF_TMEMPTR, 512);
        TC_RELINQ();
    }
    if (tid == 0) {
        MBAR_INIT(sb + OFF_MMAD + 0, 1);
        MBAR_INIT(sb + OFF_MMAD + 8, 1);
        MBAR_INIT(sb + OFF_TCMP + 0, 1);
        MBAR_INIT(sb + OFF_TCMP + 8, 1);
        asm volatile("fence.proxy.async.shared::cta;" ::: "memory");
    }
    for (int i = tid; i < N_HID; i += 256)
        ((float*)(sm + OFF_BIAS))[i] = bias[i];
    __syncthreads();
    uint32_t tmem;
    asm volatile("ld.shared.b32 %0, [%1];" : "=r"(tmem) : "r"(sb + OFF_TMEMPTR));

    int T = 0;
    for (int tau = bid; tau < NTILES; tau += NSM) T++;
    const int total = 4 * T;

    // prologue: fill chunks 0 and 1
    fill_chunk(sb, 0, bid, tid); CP_COMMIT();
    fill_chunk(sb, 1, bid, tid); CP_COMMIT();

    for (int gi = 0; gi < total; gi++) {
        const int s = gi & 1;
        const int t = gi >> 2;
        const int c = gi & 3;
        if (gi < total - 1) { CP_WAIT(1); } else { CP_WAIT(0); }
        __syncthreads();                     // chunk gi fully in smem
        if (tid == 0) {
            asm volatile("fence.proxy.async.shared::cta;" ::: "memory");
            uint64_t dA[2] = { make_desc_sw128(sb + s * STAGE),
                               make_desc_sw128(sb + s * STAGE + ST_A) };
            uint64_t dB[2] = { make_desc_sw128(sb + s * STAGE + 2 * ST_A),
                               make_desc_sw128(sb + s * STAGE + 2 * ST_A + ST_B) };
            const uint32_t dacc = tmem + (uint32_t)((t & 1) * 256);
#pragma unroll
            for (int p = 0; p < 3; p++) {
                uint64_t ad = dA[p == 2 ? 1 : 0];
                uint64_t bd = dB[p == 1 ? 1 : 0];
#pragma unroll
                for (int k = 0; k < 4; k++) {
                    uint32_t en = (c == 0 && p == 0 && k == 0) ? 0u : 1u;
                    mma_f16_ss(dacc, ad + 2 * k, bd + 2 * k, IDESC, en);
                }
            }
            TC_COMMIT(sb + OFF_MMAD + s * 8);
            if (c == 3) TC_COMMIT(sb + OFF_TCMP + (t & 1) * 8);
        }
        if (gi + 2 < total) {
            // stage s reusable once chunk gi's MMAs complete
            MBAR_WAIT(sb + OFF_MMAD + s * 8, (gi >> 1) & 1);
            fill_chunk(sb, gi + 2, bid, tid);
            CP_COMMIT();
        }
        // overlapped epilogue: previous tile, other TMEM half
        if (c == 0 && t > 0)
            epilogue_tile(sm, sb, tmem, C, t - 1, bid, warp, lane);
    }
    epilogue_tile(sm, sb, tmem, C, T - 1, bid, warp, lane);

    __syncthreads();
    if (warp == 0) TC_DEALLOC(tmem, 512);
#else
    // Portable-PTX fallback (never used when the sm_103a cubin loads). Slow but correct.
    const int tid = threadIdx.x;
    for (int tau = blockIdx.x; tau < NTILES; tau += gridDim.x) {
        const int n0 = (tau % NTN) * GBN, m0 = (tau / NTN) * GBM;
        for (int idx = tid; idx < GBM * GBN; idx += blockDim.x) {
            int mi = idx / GBN, ni = idx - mi * GBN;
            int tm = (m0 + mi) >> 7, rim = (m0 + mi) & 127;
            int tn = (n0 + ni) >> 8, rin = (n0 + ni) & 255;
            float acc = 0.0f;
            for (int k = 0; k < KP; k++) {
                int ch = k >> 6, kk = k & 63, uc = kk >> 3, e = kk & 7;
                uint32_t offa = (uint32_t)(rim * 128 + uc * 16);
                offa = (offa ^ ((offa >> 3) & 0x70)) + e * 2;
                uint32_t offb = (uint32_t)(rin * 128 + uc * 16);
                offb = (offb ^ ((offb >> 3) & 0x70)) + e * 2;
                const __nv_bfloat16* Ah = (const __nv_bfloat16*)((const char*)g_Atiles +
                    (((size_t)tm * NCH + ch) * 2) * ABLK + offa);
                const __nv_bfloat16* Al = (const __nv_bfloat16*)((const char*)Ah + ABLK);
                const __nv_bfloat16* Bh = (const __nv_bfloat16*)((const char*)g_Btiles +
                    (((size_t)tn * NCH + ch) * 2) * BBLK + offb);
                const __nv_bfloat16* Bl = (const __nv_bfloat16*)((const char*)Bh + BBLK);
                float a = __bfloat162float(*Ah) + __bfloat162float(*Al);
                float w = __bfloat162float(*Bh) + __bfloat162float(*Bl);
                acc += a * w;
            }
            C[(size_t)(m0 + mi) * N_HID + n0 + ni] = fmaxf(acc + bias[n0 + ni], 0.0f);
        }
    }
#endif
}

// ---------------------------------------------------------------------------
extern "C" void kernel_launch(void* const* d_in, const int* in_sizes, int n_in,
                              void* d_out, int out_size) {
    const int*   ids32 = nullptr;
    const float* table = nullptr;
    const float* W     = nullptr;
    const float* b     = nullptr;
    for (int i = 0; i < n_in; i++) {
        if (in_sizes[i] == M_IDS * 2)                   ids32 = (const int*)d_in[i];
        else if (in_sizes[i] == NQUER * NDOCS * K_FEAT) table = (const float*)d_in[i];
        else if (in_sizes[i] == N_HID * K_FEAT)         W     = (const float*)d_in[i];
        else if (in_sizes[i] == N_HID)                  b     = (const float*)d_in[i];
    }

    float* out    = (float*)d_out;
    float* C      = out;                               // [65536, 768]
    float* fb_out = out + (size_t)M_IDS * N_HID;       // [65536, 220]
    int write_fb  = (out_size >= M_IDS * (N_HID + K_FEAT)) ? 1 : 0;

    cudaFuncSetAttribute(gemm_tc_kernel,
                         cudaFuncAttributeMaxDynamicSharedMemorySize, SMEM_TOTAL);

    detect_ids_kernel<<<1, 32>>>(ids32);
    wprep_kernel<<<N_HID / 8, 256>>>(W);
    gather_transform_kernel<<<M_IDS / 8, 256>>>(ids32, table, fb_out, write_fb);

    gemm_tc_kernel<<<NSM, 256, SMEM_TOTAL>>>(b, C);
}

// round 17
// speedup vs baseline: 2.1893x; 1.0782x over previous
#include <cuda_runtime.h>
#include <cuda_bf16.h>
#include <cstdint>

#define M_IDS   65536
#define N_HID   768
#define K_FEAT  220
#define KP      256
#define NDOCS   128
#define NQUER   2000

#define GBM 128
#define GBN 128
#define KC  64
#define NCH (KP / KC)            // 4
#define NTM (M_IDS / GBM)        // 512 m-tiles
#define NTN (N_HID / GBN)        // 6 n-tiles
#define NTILES (NTM * NTN)       // 3072
#define NSM 148
#define ABLK 16384               // A plane block: 128 rows x 128B (swizzled image)
#define BBLK 16384               // B plane block: 128 rows x 128B (swizzled image)

// ---------------- scratch (__device__ globals; no allocation allowed) -------
__device__ uint4 g_Atiles[(size_t)NTM * NCH * 2 * (ABLK / 16)];   // 64 MB
__device__ uint4 g_Btiles[(size_t)NTN * NCH * 2 * (BBLK / 16)];   // 768 KB
__device__ int g_ids_is_i32;

// tcgen05 is arch-accelerated: only in the sm_103a pass, not compute_103 PTX.
#if defined(__CUDA_ARCH__) && defined(__CUDA_ARCH_FEAT_SM103_ALL)
#define HAS_TCGEN05 1
#else
#define HAS_TCGEN05 0
#endif

__device__ __forceinline__ uint32_t smem_u32(const void* p) {
    uint32_t a;
    asm("{ .reg .u64 t; cvta.to.shared.u64 t, %1; cvt.u32.u64 %0, t; }" : "=r"(a) : "l"(p));
    return a;
}

#if HAS_TCGEN05

#define MBAR_INIT(addr, cnt) \
    asm volatile("mbarrier.init.shared.b64 [%0], %1;" :: "r"(addr), "r"(cnt) : "memory")

#define MBAR_WAIT(addr, par) do {                                              \
    uint32_t _m = (addr); uint32_t _p = (par); uint32_t _done;                 \
    asm volatile("{\n\t.reg .pred p;\n\t"                                      \
        "mbarrier.try_wait.parity.acquire.cta.shared::cta.b64 p, [%1], %2;\n\t"\
        "selp.b32 %0, 1, 0, p;\n\t}"                                           \
        : "=r"(_done) : "r"(_m), "r"(_p) : "memory");                          \
    if (!_done) {                                                              \
        asm volatile("{\n\t.reg .pred P1;\n\t"                                 \
            "W_%=:\n\t"                                                        \
            "mbarrier.try_wait.parity.acquire.cta.shared::cta.b64 P1, [%0], %1, 0x989680;\n\t" \
            "@P1 bra.uni D_%=;\n\t"                                            \
            "bra.uni W_%=;\n\t"                                                \
            "D_%=:\n\t}" :: "r"(_m), "r"(_p) : "memory");                      \
    }                                                                          \
} while (0)

// 16B async copy, L1-bypass; completion via commit_group/wait_group
#define CP16(dst, src) \
    asm volatile("cp.async.cg.shared.global [%0], [%1], 16;" :: "r"(dst), "l"(src) : "memory")
#define CP_COMMIT() asm volatile("cp.async.commit_group;" ::: "memory")
#define CP_WAIT(n)  asm volatile("cp.async.wait_group %0;" :: "n"(n) : "memory")

// 64-bit SMEM descriptor: SW128, version=1 (Blackwell), LBO=1, SBO=64
__device__ __forceinline__ uint64_t make_desc_sw128(uint32_t addr) {
    const uint64_t base = (uint64_t(2) << 61) | (uint64_t(1) << 46)
                        | (uint64_t(64) << 32) | (uint64_t(1) << 16);
    return base | ((uint64_t)(addr >> 4) & 0x3FFF);
}

__device__ __forceinline__ void mma_f16_ss(uint32_t d_tmem, uint64_t a_desc,
                                           uint64_t b_desc, uint32_t idesc,
                                           uint32_t enable) {
    asm volatile(
        "{\n\t.reg .pred p;\n\t"
        "setp.ne.u32 p, %5, 0;\n\t"
        "tcgen05.mma.cta_group::1.kind::f16 [%0], %1, %2, %3, {%4, %4, %4, %4}, p;\n\t"
        "}"
        :: "r"(d_tmem), "l"(a_desc), "l"(b_desc), "r"(idesc), "r"(0u), "r"(enable)
        : "memory");
}

#define TC_COMMIT(mbar) \
    asm volatile("tcgen05.commit.cta_group::1.mbarrier::arrive::one.shared::cluster.b64 [%0];" \
                 :: "r"(mbar) : "memory")
#define TC_ALLOC(smem_res, n) \
    asm volatile("tcgen05.alloc.cta_group::1.sync.aligned.shared::cta.b32 [%0], %1;" \
                 :: "r"(smem_res), "r"(n) : "memory")
#define TC_RELINQ() \
    asm volatile("tcgen05.relinquish_alloc_permit.cta_group::1.sync.aligned;")
#define TC_DEALLOC(tmem, n) \
    asm volatile("tcgen05.dealloc.cta_group::1.sync.aligned.b32 %0, %1;" :: "r"(tmem), "r"(n))
#define TC_FENCE_AFTER()  asm volatile("tcgen05.fence::after_thread_sync;" ::: "memory")
#define TC_FENCE_BEFORE() asm volatile("tcgen05.fence::before_thread_sync;" ::: "memory")
#define TC_WAIT_LD()      asm volatile("tcgen05.wait::ld.sync.aligned;" ::: "memory")

#define TC_LD_X32(r, addr)                                                     \
    asm volatile("tcgen05.ld.sync.aligned.32x32b.x32.b32 "                     \
        "{%0,%1,%2,%3,%4,%5,%6,%7,%8,%9,%10,%11,%12,%13,%14,%15,"              \
        "%16,%17,%18,%19,%20,%21,%22,%23,%24,%25,%26,%27,%28,%29,%30,%31}, [%32];" \
        : "=r"((r)[0]),"=r"((r)[1]),"=r"((r)[2]),"=r"((r)[3]),                 \
          "=r"((r)[4]),"=r"((r)[5]),"=r"((r)[6]),"=r"((r)[7]),                 \
          "=r"((r)[8]),"=r"((r)[9]),"=r"((r)[10]),"=r"((r)[11]),               \
          "=r"((r)[12]),"=r"((r)[13]),"=r"((r)[14]),"=r"((r)[15]),             \
          "=r"((r)[16]),"=r"((r)[17]),"=r"((r)[18]),"=r"((r)[19]),             \
          "=r"((r)[20]),"=r"((r)[21]),"=r"((r)[22]),"=r"((r)[23]),             \
          "=r"((r)[24]),"=r"((r)[25]),"=r"((r)[26]),"=r"((r)[27]),             \
          "=r"((r)[28]),"=r"((r)[29]),"=r"((r)[30]),"=r"((r)[31])              \
        : "r"(addr))

#endif  // HAS_TCGEN05

// ---------------------------------------------------------------------------
// Kernel 0: ids layout detection (int64 LE vs int32 pairs)
// ---------------------------------------------------------------------------
__global__ void detect_ids_kernel(const int* __restrict__ w) {
    int any = 0;
    for (int i = threadIdx.x; i < 2048; i += 32) any |= w[2 * i + 1];
    any = __reduce_or_sync(0xffffffffu, any);
    if (threadIdx.x == 0) g_ids_is_i32 = (any != 0) ? 1 : 0;
}

// ---------------------------------------------------------------------------
// hi/lo split helpers
// ---------------------------------------------------------------------------
__device__ __forceinline__ uint32_t pack2bf(float a, float b) {
    __nv_bfloat162 t = __floats2bfloat162_rn(a, b);
    return *(uint32_t*)&t;
}

__device__ __forceinline__ void split8(const float4& v0, const float4& v1,
                                       uint4& hi, uint4& lo) {
    __nv_bfloat16 h[8];
    float f[8] = { v0.x, v0.y, v0.z, v0.w, v1.x, v1.y, v1.z, v1.w };
    float l[8];
#pragma unroll
    for (int i = 0; i < 8; i++) {
        h[i] = __float2bfloat16(f[i]);
        l[i] = f[i] - __bfloat162float(h[i]);
    }
    hi.x = pack2bf(__bfloat162float(h[0]), __bfloat162float(h[1]));
    hi.y = pack2bf(__bfloat162float(h[2]), __bfloat162float(h[3]));
    hi.z = pack2bf(__bfloat162float(h[4]), __bfloat162float(h[5]));
    hi.w = pack2bf(__bfloat162float(h[6]), __bfloat162float(h[7]));
    lo.x = pack2bf(l[0], l[1]);
    lo.y = pack2bf(l[2], l[3]);
    lo.z = pack2bf(l[4], l[5]);
    lo.w = pack2bf(l[6], l[7]);
}

// ---------------------------------------------------------------------------
// Kernel 1: W -> tiled swizzled bf16 hi/lo block images (128-row n-tiles)
// ---------------------------------------------------------------------------
__global__ __launch_bounds__(256)
void wprep_kernel(const float* __restrict__ W) {
    int row = blockIdx.x * 8 + (threadIdx.x >> 5);
    int j   = threadIdx.x & 31;
    const float4* src = (const float4*)(W + (size_t)row * K_FEAT);
    float4 z = make_float4(0.f, 0.f, 0.f, 0.f);
    float4 x0 = (8 * j + 3 < K_FEAT) ? src[2 * j]     : z;
    float4 x1 = (8 * j + 7 < K_FEAT) ? src[2 * j + 1] : z;
    uint4 hi, lo;
    split8(x0, x1, hi, lo);

    int tn = row >> 7, rn = row & 127;
    int c = j >> 3, uc = j & 7;
    uint32_t off = (uint32_t)(rn * 128 + uc * 16);
    uint32_t swz = off ^ ((off >> 3) & 0x70);
    size_t base = ((((size_t)tn * NCH + c) * 2) * BBLK + swz) >> 4;
    g_Btiles[base] = hi;
    g_Btiles[base + BBLK / 16] = lo;
}

// ---------------------------------------------------------------------------
// Kernel 2: gather + log1p(|x|)*sign(x) -> fb + tiled swizzled hi/lo images
// ---------------------------------------------------------------------------
__global__ __launch_bounds__(256)
void gather_transform_kernel(const int* __restrict__ ids32,
                             const float* __restrict__ table,
                             float* __restrict__ fb, int write_fb) {
    int r = blockIdx.x * 8 + (threadIdx.x >> 5);
    int j = threadIdx.x & 31;
    int q, d;
    if (g_ids_is_i32) { q = ids32[2 * r]; d = ids32[2 * r + 1]; }
    else              { q = ids32[4 * r]; d = ids32[4 * r + 2]; }
    q = min(max(q, 0), NQUER - 1);
    d = min(max(d, 0), NDOCS - 1);
    const float4* src = (const float4*)(table + ((size_t)q * NDOCS + d) * K_FEAT);

    float4 z = make_float4(0.f, 0.f, 0.f, 0.f);
    bool v0ok = (8 * j + 3 < K_FEAT), v1ok = (8 * j + 7 < K_FEAT);
    float4 x0 = v0ok ? src[2 * j]     : z;
    float4 x1 = v1ok ? src[2 * j + 1] : z;
    float4 v0, v1;
    v0.x = copysignf(__logf(fabsf(x0.x) + 1.0f), x0.x);
    v0.y = copysignf(__logf(fabsf(x0.y) + 1.0f), x0.y);
    v0.z = copysignf(__logf(fabsf(x0.z) + 1.0f), x0.z);
    v0.w = copysignf(__logf(fabsf(x0.w) + 1.0f), x0.w);
    v1.x = copysignf(__logf(fabsf(x1.x) + 1.0f), x1.x);
    v1.y = copysignf(__logf(fabsf(x1.y) + 1.0f), x1.y);
    v1.z = copysignf(__logf(fabsf(x1.z) + 1.0f), x1.z);
    v1.w = copysignf(__logf(fabsf(x1.w) + 1.0f), x1.w);
    if (write_fb) {
        if (v0ok) *(float4*)&fb[(size_t)r * K_FEAT + 8 * j]     = v0;
        if (v1ok) *(float4*)&fb[(size_t)r * K_FEAT + 8 * j + 4] = v1;
    }

    uint4 hi, lo;
    split8(v0, v1, hi, lo);

    int tm = r >> 7, ri = r & 127;
    int c = j >> 3, uc = j & 7;
    uint32_t off = (uint32_t)(ri * 128 + uc * 16);
    uint32_t swz = off ^ ((off >> 3) & 0x70);
    size_t base = ((((size_t)tm * NCH + c) * 2) * ABLK + swz) >> 4;
    g_Atiles[base] = hi;
    g_Atiles[base + ABLK / 16] = lo;
}

// ---------------------------------------------------------------------------
// Kernel 3: persistent tcgen05 GEMM, 3-stage cp.async pipeline, TMEM dbl-buf
// ---------------------------------------------------------------------------
#define ST_A ABLK                // 16 KB
#define ST_B BBLK                // 16 KB
#define STAGE (2*ST_A + 2*ST_B)  // 65536
#define NSTG 3
#define AUX (NSTG * STAGE)       // 196608
#define OFF_TMEMPTR (AUX + 0)
#define OFF_MMAD    (AUX + 8)    // mmad[0]=+8, mmad[1]=+16
#define OFF_TCMP    (AUX + 24)   // tilecomp[0]=+24, tilecomp[1]=+32
#define OFF_BIAS    (AUX + 128)
#define SMEM_TOTAL  (AUX + 128 + N_HID * 4)

static constexpr uint32_t IDESC =
    (1u << 4) | (1u << 7) | (1u << 10) | ((GBN / 8) << 17) | ((GBM / 16) << 24);

#if HAS_TCGEN05
// Copy chunk gi's pre-swizzled images into its stage (all 256 threads).
__device__ __forceinline__ void fill_chunk(uint32_t sb, int gi, int bid, int tid) {
    const int tau = bid + (gi >> 2) * NSM;
    const int c   = gi & 3;
    const uint32_t sbase = sb + (gi % NSTG) * STAGE;
    const char* As = (const char*)g_Atiles + ((size_t)(tau / NTN) * (NCH * 2) + c * 2) * ABLK;
    const char* Bs = (const char*)g_Btiles + ((size_t)(tau % NTN) * (NCH * 2) + c * 2) * BBLK;
#pragma unroll
    for (int k = 0; k < 8; k++) {
        int i = tid + k * 256;              // 0..2047
        int pl = i >> 10, w = i & 1023;
        CP16(sbase + pl * ST_A + w * 16, As + (size_t)pl * ABLK + (size_t)w * 16);
    }
#pragma unroll
    for (int k = 0; k < 8; k++) {
        int i = tid + k * 256;              // 0..2047
        int pl = i >> 10, w = i & 1023;
        CP16(sbase + 2 * ST_A + pl * ST_B + w * 16, Bs + (size_t)pl * BBLK + (size_t)w * 16);
    }
}

// Epilogue for local tile t: wait tilecomp[t&1], LDTM + bias + relu + store.
__device__ __forceinline__ void epilogue_tile(const char* smc, uint32_t sb, uint32_t tmem,
                                              float* C, int t, int bid,
                                              int warp, int lane) {
    const int tau = bid + t * NSM;
    const int n0  = (tau % NTN) * GBN;
    const int m0  = (tau / NTN) * GBM;
    MBAR_WAIT(sb + OFF_TCMP + (t & 1) * 8, (t >> 1) & 1);
    TC_FENCE_AFTER();
    const uint32_t acc = tmem + (uint32_t)((t & 1) * GBN);
    const int halfw = warp >> 2;
    const int mrow = m0 + (warp & 3) * 32 + lane;
    const float* bs = (const float*)(smc + OFF_BIAS) + n0;
#pragma unroll
    for (int p = 0; p < 2; p++) {
        const int cb = halfw * 64 + p * 32;
        uint32_t r[32];
        TC_LD_X32(r, acc + cb);
        TC_WAIT_LD();
        float o[32];
#pragma unroll
        for (int cc = 0; cc < 32; cc++)
            o[cc] = fmaxf(__uint_as_float(r[cc]) + bs[cb + cc], 0.0f);
        float* dst = &C[(size_t)mrow * N_HID + n0 + cb];
#pragma unroll
        for (int v4 = 0; v4 < 8; v4++) {
            float4 tv = make_float4(o[v4 * 4], o[v4 * 4 + 1], o[v4 * 4 + 2], o[v4 * 4 + 3]);
            *(float4*)&dst[v4 * 4] = tv;
        }
    }
    TC_FENCE_BEFORE();
}
#endif

__global__ __launch_bounds__(256, 1)
void gemm_tc_kernel(const float* __restrict__ bias, float* __restrict__ C) {
#if HAS_TCGEN05
    extern __shared__ char sm[];
    const uint32_t sb = smem_u32(sm);
    const int tid = threadIdx.x;
    const int warp = tid >> 5, lane = tid & 31;
    const int bid = blockIdx.x;

    if (warp == 0) {
        TC_ALLOC(sb + OFF_TMEMPTR, 256);
        TC_RELINQ();
    }
    if (tid == 0) {
        MBAR_INIT(sb + OFF_MMAD + 0, 1);
        MBAR_INIT(sb + OFF_MMAD + 8, 1);
        MBAR_INIT(sb + OFF_TCMP + 0, 1);
        MBAR_INIT(sb + OFF_TCMP + 8, 1);
        asm volatile("fence.proxy.async.shared::cta;" ::: "memory");
    }
    for (int i = tid; i < N_HID; i += 256)
        ((float*)(sm + OFF_BIAS))[i] = bias[i];
    __syncthreads();
    uint32_t tmem;
    asm volatile("ld.shared.b32 %0, [%1];" : "=r"(tmem) : "r"(sb + OFF_TMEMPTR));

    int T = 0;
    for (int tau = bid; tau < NTILES; tau += NSM) T++;
    const int total = 4 * T;

    // prologue: fill chunks 0 and 1 (chunk 2 filled inside loop at gi=0)
    fill_chunk(sb, 0, bid, tid); CP_COMMIT();
    if (total > 1) { fill_chunk(sb, 1, bid, tid); CP_COMMIT(); }

    for (int gi = 0; gi < total; gi++) {
        const int s = gi % NSTG;
        const int t = gi >> 2;
        const int c = gi & 3;
        if (gi < total - 1) { CP_WAIT(1); } else { CP_WAIT(0); }
        __syncthreads();                     // chunk gi fully in smem
        if (tid == 0) {
            asm volatile("fence.proxy.async.shared::cta;" ::: "memory");
            uint64_t dA[2] = { make_desc_sw128(sb + s * STAGE),
                               make_desc_sw128(sb + s * STAGE + ST_A) };
            uint64_t dB[2] = { make_desc_sw128(sb + s * STAGE + 2 * ST_A),
                               make_desc_sw128(sb + s * STAGE + 2 * ST_A + ST_B) };
            const uint32_t dacc = tmem + (uint32_t)((t & 1) * GBN);
#pragma unroll
            for (int p = 0; p < 3; p++) {
                uint64_t ad = dA[p == 2 ? 1 : 0];
                uint64_t bd = dB[p == 1 ? 1 : 0];
#pragma unroll
                for (int k = 0; k < 4; k++) {
                    uint32_t en = (c == 0 && p == 0 && k == 0) ? 0u : 1u;
                    mma_f16_ss(dacc, ad + 2 * k, bd + 2 * k, IDESC, en);
                }
            }
            TC_COMMIT(sb + OFF_MMAD + (gi & 1) * 8);
            if (c == 3) TC_COMMIT(sb + OFF_TCMP + (t & 1) * 8);
        }
        // fill chunk gi+2 into stage (gi+2)%3 == stage of chunk gi-1:
        // wait MMA(gi-1) (issued LAST iteration -> wait nearly free)
        if (gi + 2 < total) {
            if (gi >= 1)
                MBAR_WAIT(sb + OFF_MMAD + ((gi - 1) & 1) * 8, ((gi - 1) >> 1) & 1);
            fill_chunk(sb, gi + 2, bid, tid);
            CP_COMMIT();
        }
        // overlapped epilogue: previous tile, other TMEM half
        if (c == 0 && t > 0)
            epilogue_tile(sm, sb, tmem, C, t - 1, bid, warp, lane);
    }
    epilogue_tile(sm, sb, tmem, C, T - 1, bid, warp, lane);

    __syncthreads();
    if (warp == 0) TC_DEALLOC(tmem, 256);
#else
    // Portable-PTX fallback (never used when the sm_103a cubin loads). Slow but correct.
    const int tid = threadIdx.x;
    for (int tau = blockIdx.x; tau < NTILES; tau += gridDim.x) {
        const int n0 = (tau % NTN) * GBN, m0 = (tau / NTN) * GBM;
        for (int idx = tid; idx < GBM * GBN; idx += blockDim.x) {
            int mi = idx / GBN, ni = idx - mi * GBN;
            int tm = (m0 + mi) >> 7, rim = (m0 + mi) & 127;
            int tn = (n0 + ni) >> 7, rin = (n0 + ni) & 127;
            float acc = 0.0f;
            for (int k = 0; k < KP; k++) {
                int ch = k >> 6, kk = k & 63, uc = kk >> 3, e = kk & 7;
                uint32_t offa = (uint32_t)(rim * 128 + uc * 16);
                offa = (offa ^ ((offa >> 3) & 0x70)) + e * 2;
                uint32_t offb = (uint32_t)(rin * 128 + uc * 16);
                offb = (offb ^ ((offb >> 3) & 0x70)) + e * 2;
                const __nv_bfloat16* Ah = (const __nv_bfloat16*)((const char*)g_Atiles +
                    (((size_t)tm * NCH + ch) * 2) * ABLK + offa);
                const __nv_bfloat16* Al = (const __nv_bfloat16*)((const char*)Ah + ABLK);
                const __nv_bfloat16* Bh = (const __nv_bfloat16*)((const char*)g_Btiles +
                    (((size_t)tn * NCH + ch) * 2) * BBLK + offb);
                const __nv_bfloat16* Bl = (const __nv_bfloat16*)((const char*)Bh + BBLK);
                float a = __bfloat162float(*Ah) + __bfloat162float(*Al);
                float w = __bfloat162float(*Bh) + __bfloat162float(*Bl);
                acc += a * w;
            }
            C[(size_t)(m0 + mi) * N_HID + n0 + ni] = fmaxf(acc + bias[n0 + ni], 0.0f);
        }
    }
#endif
}

// ---------------------------------------------------------------------------
extern "C" void kernel_launch(void* const* d_in, const int* in_sizes, int n_in,
                              void* d_out, int out_size) {
    const int*   ids32 = nullptr;
    const float* table = nullptr;
    const float* W     = nullptr;
    const float* b     = nullptr;
    for (int i = 0; i < n_in; i++) {
        if (in_sizes[i] == M_IDS * 2)                   ids32 = (const int*)d_in[i];
        else if (in_sizes[i] == NQUER * NDOCS * K_FEAT) table = (const float*)d_in[i];
        else if (in_sizes[i] == N_HID * K_FEAT)         W     = (const float*)d_in[i];
        else if (in_sizes[i] == N_HID)                  b     = (const float*)d_in[i];
    }

    float* out    = (float*)d_out;
    float* C      = out;                               // [65536, 768]
    float* fb_out = out + (size_t)M_IDS * N_HID;       // [65536, 220]
    int write_fb  = (out_size >= M_IDS * (N_HID + K_FEAT)) ? 1 : 0;

    cudaFuncSetAttribute(gemm_tc_kernel,
                         cudaFuncAttributeMaxDynamicSharedMemorySize, SMEM_TOTAL);

    detect_ids_kernel<<<1, 32>>>(ids32);
    wprep_kernel<<<N_HID / 8, 256>>>(W);
    gather_transform_kernel<<<M_IDS / 8, 256>>>(ids32, table, fb_out, write_fb);

    gemm_tc_kernel<<<NSM, 256, SMEM_TOTAL>>>(b, C);
}